// round 17
// baseline (speedup 1.0000x reference)
#include <cuda_runtime.h>

// FasterTensorProduct, factored form:
//   out[b,n1,n2,o] = sum_{s=0..3} sh[b,n1,s] * P[b,n2,s,o]
// where P[b,n2,s,:] = y(x_{b,n2}, e_s) is the bilinear map on the 4 sh basis
// vectors.
//
// Single fused kernel, 512 blocks x 544 threads.
// Phase 1: TWO threads per output column o (h = tid/272 picks the k-range
// half) -> per-thread weight-load chain halved vs the 19.2us fused kernel.
// Partials (scaled+permuted, hence additive) go to smem part[h][s][o] (SoA,
// conflict-free). x is read directly from global (warp-broadcast, L1-hot):
// no smem staging, no barrier before phase 1, loads issue from instr 0.
// Phase 2: proven fan-out; q vectors = part[0]+part[1] via 8 LDS.128.
//
// Dims: M0E=64, M1O=32, M1E=32, M0O=16, IN_DIM=OUT_DIM=272, B=4, N=128.
// Weights (flat, row-major, each block scaled by 1/sqrt(rows)):
//   W0e at 0     : (96,64)
//   W1o at 6144  : (128,32)
//   W1e at 10240 : (80,32)
//   W0o at 12800 : (48,16)

#define B_DIM 4
#define N_DIM 128
#define IO_DIM 272
#define W_NUMEL 13568
#define THREADS 544

__global__ __launch_bounds__(THREADS, 2) void ftp_fused_split(
    const float* __restrict__ in_, const float4* __restrict__ sh4,
    const float* __restrict__ w, float4* __restrict__ outv)
{
    __shared__ float  part[2 * 4 * IO_DIM];   // part[(h*4+s)*272 + o]
    __shared__ float4 shs[N_DIM];

    const int tid = threadIdx.x;
    const int n2  = blockIdx.x;
    const int b   = blockIdx.y;

    if (tid < N_DIM)
        shs[tid] = sh4[b * N_DIM + tid];

    const float* __restrict__ x = in_ + (size_t)(b * N_DIM + n2) * IO_DIM;

    const float inv2 = 0.7071067811865476f;   // 1/sqrt(2)
    const float inv3 = 0.5773502691896258f;   // 1/sqrt(3)

    // ---- phase 1: thread (h, o) computes k-half h of column o ----
    const int h = tid / IO_DIM;   // 0 or 1
    const int o = tid - h * IO_DIM;

    float p0, p1, p2, p3;

    if (o < 64) {
        // y0e: out0e = [x0e*sh0, (x1o . sh1)/sqrt3], W0e (96,64), 1/sqrt(96)
        const float s = 0.10206207261596575f;
        float a0 = 0.f, a1 = 0.f, a2 = 0.f, a3 = 0.f;
        const int k0 = h * 32, m0 = h * 16;
        #pragma unroll
        for (int k = 0; k < 32; k++) a0 += x[k0 + k] * w[(k0 + k) * 64 + o];
        #pragma unroll
        for (int m = 0; m < 16; m++) {
            float wv = w[(64 + m0 + m) * 64 + o];
            a1 += x[64 + 3 * (m0 + m) + 0] * wv;
            a2 += x[64 + 3 * (m0 + m) + 1] * wv;
            a3 += x[64 + 3 * (m0 + m) + 2] * wv;
        }
        p0 = a0 * s;
        p1 = a1 * (s * inv3);
        p2 = a2 * (s * inv3);
        p3 = a3 * (s * inv3);
    } else if (o < 160) {
        // y1o: o = 64 + oo*3 + cp. W1o (128,32) at 6144, 1/sqrt(128)
        // rows: [0:64) x0e*sh1[c], [64:96) x1o*sh0, [96:128) cross(x1e,sh1)/sqrt2
        const float s  = 0.08838834764831845f;
        const int  t  = o - 64;
        const int  oo = t / 3;
        const int  cp = t - 3 * oo;
        const int  ca = (cp + 1) % 3;
        const int  cb = (cp + 2) % 3;
        const float* w1 = w + 6144;
        const int k0 = h * 32, m0 = h * 16;
        float A = 0.f, Bacc = 0.f, Ca = 0.f, Cb = 0.f;
        #pragma unroll
        for (int k = 0; k < 32; k++) Bacc += x[k0 + k] * w1[(k0 + k) * 32 + oo];
        #pragma unroll
        for (int m = 0; m < 16; m++) {
            const int mm = m0 + m;
            A += x[64 + 3 * mm + cp] * w1[(64 + mm) * 32 + oo];
            float wv = w1[(96 + mm) * 32 + oo];
            Ca += x[160 + 3 * mm + cb] * wv;   // cross(x1e, e_ca)[cp] = -x1e[cb]
            Cb += x[160 + 3 * mm + ca] * wv;   // cross(x1e, e_cb)[cp] = +x1e[ca]
        }
        p0 = A * s;
        float vB = Bacc * s;
        float vA = -Ca * (s * inv2);
        float vC =  Cb * (s * inv2);
        p1 = (cp == 0) ? vB : ((ca == 0) ? vA : vC);
        p2 = (cp == 1) ? vB : ((ca == 1) ? vA : vC);
        p3 = (cp == 2) ? vB : ((ca == 2) ? vA : vC);
    } else if (o < 256) {
        // y1e: o = 160 + oo*3 + cp. W1e (80,32) at 10240, 1/sqrt(80)
        // rows: [0:32) cross(x1o,sh1)/sqrt2, [32:64) x1e*sh0, [64:80) x0o*sh1[c]
        const float s  = 0.11180339887498949f;
        const int  t  = o - 160;
        const int  oo = t / 3;
        const int  cp = t - 3 * oo;
        const int  ca = (cp + 1) % 3;
        const int  cb = (cp + 2) % 3;
        const float* w2 = w + 10240;
        const int m0 = h * 16, k0 = h * 8;
        float A = 0.f, Bacc = 0.f, Ca = 0.f, Cb = 0.f;
        #pragma unroll
        for (int m = 0; m < 16; m++) {
            const int mm = m0 + m;
            A += x[160 + 3 * mm + cp] * w2[(32 + mm) * 32 + oo];
            float wv = w2[mm * 32 + oo];
            Ca += x[64 + 3 * mm + cb] * wv;
            Cb += x[64 + 3 * mm + ca] * wv;
        }
        #pragma unroll
        for (int k = 0; k < 8; k++)
            Bacc += x[256 + k0 + k] * w2[(64 + k0 + k) * 32 + oo];
        p0 = A * s;
        float vB = Bacc * s;
        float vA = -Ca * (s * inv2);
        float vC =  Cb * (s * inv2);
        p1 = (cp == 0) ? vB : ((ca == 0) ? vA : vC);
        p2 = (cp == 1) ? vB : ((ca == 1) ? vA : vC);
        p3 = (cp == 2) ? vB : ((ca == 2) ? vA : vC);
    } else {
        // y0o: o = 256 + oy. W0o (48,16) at 12800, 1/sqrt(48)
        const float s  = 0.14433756729740645f;
        const int  oy = o - 256;
        const float* w3 = w + 12800;
        const int k0 = h * 8, m0 = h * 16;
        float a0 = 0.f, a1 = 0.f, a2 = 0.f, a3 = 0.f;
        #pragma unroll
        for (int k = 0; k < 8; k++)
            a0 += x[256 + k0 + k] * w3[(32 + k0 + k) * 16 + oy];
        #pragma unroll
        for (int m = 0; m < 16; m++) {
            const int mm = m0 + m;
            float wv = w3[mm * 16 + oy];
            a1 += x[160 + 3 * mm + 0] * wv;
            a2 += x[160 + 3 * mm + 1] * wv;
            a3 += x[160 + 3 * mm + 2] * wv;
        }
        p0 = a0 * s;
        p1 = a1 * (s * inv3);
        p2 = a2 * (s * inv3);
        p3 = a3 * (s * inv3);
    }

    // SoA partial store: stride-1 across lanes, conflict-free
    part[(h * 4 + 0) * IO_DIM + o] = p0;
    part[(h * 4 + 1) * IO_DIM + o] = p1;
    part[(h * 4 + 2) * IO_DIM + o] = p2;
    part[(h * 4 + 3) * IO_DIM + o] = p3;

    __syncthreads();

    // ---- phase 2: fan-out over all 128 n1 rows ----
    const int o4 = tid % 68;   // float4 column of the 272-wide output row
    const int g  = tid / 68;   // 0..7

    // q_s = part[0][s][4o4..] + part[1][s][4o4..]  (8 conflict-free LDS.128)
    float4 q0, q1, q2, q3;
    {
        const float4* pa = reinterpret_cast<const float4*>(part) ;
        // float4 index: ((h*4+s)*272 + 4*o4) / 4 = (h*4+s)*68 + o4
        float4 a0 = pa[(0 * 4 + 0) * 68 + o4], b0 = pa[(1 * 4 + 0) * 68 + o4];
        float4 a1 = pa[(0 * 4 + 1) * 68 + o4], b1 = pa[(1 * 4 + 1) * 68 + o4];
        float4 a2 = pa[(0 * 4 + 2) * 68 + o4], b2 = pa[(1 * 4 + 2) * 68 + o4];
        float4 a3 = pa[(0 * 4 + 3) * 68 + o4], b3 = pa[(1 * 4 + 3) * 68 + o4];
        q0 = make_float4(a0.x + b0.x, a0.y + b0.y, a0.z + b0.z, a0.w + b0.w);
        q1 = make_float4(a1.x + b1.x, a1.y + b1.y, a1.z + b1.z, a1.w + b1.w);
        q2 = make_float4(a2.x + b2.x, a2.y + b2.y, a2.z + b2.z, a2.w + b2.w);
        q3 = make_float4(a3.x + b3.x, a3.y + b3.y, a3.z + b3.z, a3.w + b3.w);
    }

    // out float4 index: ((b*128 + n1)*128 + n2)*68 + o4, n1 = g + 8*i
    size_t base = ((size_t)(b * N_DIM + g) * N_DIM + n2) * 68 + o4;
    const size_t stride = (size_t)8 * N_DIM * 68;

    #pragma unroll
    for (int i = 0; i < 16; i++) {
        float4 s4 = shs[g + 8 * i];
        float4 r;
        r.x = s4.x * q0.x + s4.y * q1.x + s4.z * q2.x + s4.w * q3.x;
        r.y = s4.x * q0.y + s4.y * q1.y + s4.z * q2.y + s4.w * q3.y;
        r.z = s4.x * q0.z + s4.y * q1.z + s4.z * q2.z + s4.w * q3.z;
        r.w = s4.x * q0.w + s4.y * q1.w + s4.z * q2.w + s4.w * q3.w;
        outv[base + (size_t)i * stride] = r;
    }
}

extern "C" void kernel_launch(void* const* d_in, const int* in_sizes, int n_in,
                              void* d_out, int out_size) {
    const float* in_ = nullptr;
    const float* sh  = nullptr;
    const float* w   = nullptr;
    for (int i = 0; i < n_in; i++) {
        if (in_sizes[i] == B_DIM * N_DIM * IO_DIM)      in_ = (const float*)d_in[i];
        else if (in_sizes[i] == B_DIM * N_DIM * 4)      sh  = (const float*)d_in[i];
        else if (in_sizes[i] == W_NUMEL)                w   = (const float*)d_in[i];
    }
    if (!in_) in_ = (const float*)d_in[0];
    if (!sh)  sh  = (const float*)d_in[1];
    if (!w)   w   = (const float*)d_in[2];

    dim3 grid(N_DIM, B_DIM);
    ftp_fused_split<<<grid, THREADS>>>(in_, (const float4*)sh, w, (float4*)d_out);
}